// round 12
// baseline (speedup 1.0000x reference)
#include <cuda_runtime.h>
#include <cuda_bf16.h>
#include <cstdint>

#define THREADS 256
#define ATTNW_SHIFT 20.0f
#define INV_SQRT_D  0.17677669529663687f
#define SQRT3       1.7320508075688772f
#define SQRT32      5.656854249492381f
#define L2E         1.4426950408889634f

// word(=float)-index smem layout
#define WG2H  0        // 128*20
#define WG2L  2560
#define WWTH  5120     // 384*20
#define WWTL  12800
#define WPHH  20480    // K tile hi: 128*20
#define WPHL  23040
#define WCTH  25600    // 32*68
#define WCTL  27776
#define F_H2X 29952
#define F_H2Y 30080
#define F_H2Z 30208
#define F_SW  30336
#define F_SWM 30464
#define F_BH  30592
#define F_WEQ 30624
// init-only raw-weight scratch beyond live data:
#define F_RQK 30720    // 8192 floats
#define F_RWV 38912    // 4096
#define F_RWH 43008    // 4096
#define SMEM_BYTES 188416

static __device__ __forceinline__ uint32_t smem_u32(const void* p) {
    uint32_t a;
    asm("{ .reg .u64 t; cvta.to.shared.u64 t, %1; cvt.u32.u64 %0, t; }" : "=r"(a) : "l"(p));
    return a;
}
static __device__ __forceinline__ uint32_t packb(float e0, float e1) {
    uint32_t r;
    asm("cvt.rn.bf16x2.f32 %0, %1, %2;" : "=r"(r) : "f"(e1), "f"(e0));
    return r;
}
static __device__ __forceinline__ void pack_hl(float v0, float v1,
                                               uint32_t& h, uint32_t& l) {
    h = packb(v0, v1);
    float h0 = __uint_as_float(h << 16);
    float h1 = __uint_as_float(h & 0xFFFF0000u);
    l = packb(v0 - h0, v1 - h1);
}
static __device__ __forceinline__ float ex2a(float x) {
    float r; asm("ex2.approx.f32 %0, %1;" : "=f"(r) : "f"(x)); return r;
}
static __device__ __forceinline__ void mma16(float* d, uint32_t a0, uint32_t a1,
                                             uint32_t a2, uint32_t a3,
                                             uint32_t b0, uint32_t b1) {
    asm volatile("mma.sync.aligned.m16n8k16.row.col.f32.bf16.bf16.f32 "
                 "{%0,%1,%2,%3}, {%4,%5,%6,%7}, {%8,%9}, {%0,%1,%2,%3};"
                 : "+f"(d[0]), "+f"(d[1]), "+f"(d[2]), "+f"(d[3])
                 : "r"(a0), "r"(a1), "r"(a2), "r"(a3), "r"(b0), "r"(b1));
}
static __device__ __forceinline__ void mma3(float* d, const uint32_t* ah,
                                            const uint32_t* al,
                                            uint32_t bh0, uint32_t bh1,
                                            uint32_t bl0, uint32_t bl1) {
    mma16(d, ah[0], ah[1], ah[2], ah[3], bh0, bh1);
    mma16(d, al[0], al[1], al[2], al[3], bh0, bh1);
    mma16(d, ah[0], ah[1], ah[2], ah[3], bl0, bl1);
}
// build A-frag (hi/lo) from two adjacent n8 accumulator tiles scaled per-row
static __device__ __forceinline__ void afrag_from_acc(const float* acc0, const float* acc1,
                                                      float s0, float s1,
                                                      uint32_t* ah, uint32_t* al) {
    pack_hl(acc0[0] * s0, acc0[1] * s0, ah[0], al[0]);
    pack_hl(acc0[2] * s1, acc0[3] * s1, ah[1], al[1]);
    pack_hl(acc1[0] * s0, acc1[1] * s0, ah[2], al[2]);
    pack_hl(acc1[2] * s1, acc1[3] * s1, ah[3], al[3]);
}
#define LDSM4(r, ba) \
    asm volatile("ldmatrix.sync.aligned.m8n8.x4.shared.b16 {%0,%1,%2,%3}, [%4];" \
                 : "=r"((r)[0]), "=r"((r)[1]), "=r"((r)[2]), "=r"((r)[3]) : "r"(ba))
#define STSM4(ba, r0, r1, r2, r3) \
    asm volatile("stmatrix.sync.aligned.m8n8.x4.shared.b16 [%0], {%1,%2,%3,%4};" \
                 :: "r"(ba), "r"(r0), "r"(r1), "r"(r2), "r"(r3))
#define STSM2T(ba, r0, r1) \
    asm volatile("stmatrix.sync.aligned.m8n8.x2.trans.shared.b16 [%0], {%1,%2};" \
                 :: "r"(ba), "r"(r0), "r"(r1))

__global__ void __launch_bounds__(THREADS, 1)
rep_bf16_kernel(const float* __restrict__ g2, const float* __restrict__ h2,
                const float* __restrict__ sw, const float* __restrict__ wqk,
                const float* __restrict__ wv, const float* __restrict__ wh,
                const float* __restrict__ bh, const float* __restrict__ weq,
                const int* __restrict__ mask, float* __restrict__ outg,
                float* __restrict__ outh)
{
    extern __shared__ __align__(16) float smf[];
    uint32_t* smu = (uint32_t*)smf;
    const uint32_t sb = smem_u32(smf);
    const int tid = threadIdx.x, w = tid >> 5, lane = tid & 31;
    const int g = lane >> 2, t = lane & 3;
    const int m0 = w * 16;
    const int loc = blockIdx.x;
    const int r8 = lane & 7, s01 = (lane >> 3) & 1, s2 = lane >> 4;

    const float* g2l = g2 + (size_t)loc * 128 * 32;
    const float* h2l = h2 + (size_t)loc * 128 * 3;
    const float* swl = sw + (size_t)loc * 128;
    const int*   ml  = mask + (size_t)loc * 128;

    // ---- stage raw weights into high scratch ----
    {
        const float4* s1 = (const float4*)wqk;
        float4* d1 = (float4*)(smf + F_RQK);
        #pragma unroll
        for (int i = 0; i < 8; ++i) d1[tid + i * 256] = s1[tid + i * 256];
        const float4* s2p = (const float4*)wv;
        float4* d2 = (float4*)(smf + F_RWV);
        #pragma unroll
        for (int i = 0; i < 4; ++i) d2[tid + i * 256] = s2p[tid + i * 256];
        const float4* s3 = (const float4*)wh;
        float4* d3 = (float4*)(smf + F_RWH);
        #pragma unroll
        for (int i = 0; i < 4; ++i) d3[tid + i * 256] = s3[tid + i * 256];
    }
    // ---- g2 -> bf16 hi/lo (thread = half row) ----
    {
        int r = tid >> 1, hf = tid & 1;
        const float* src = g2l + (size_t)r * 32 + hf * 16;
        float e[16];
        #pragma unroll
        for (int i = 0; i < 4; ++i) {
            float4 v = ((const float4*)src)[i];
            e[4*i] = v.x; e[4*i+1] = v.y; e[4*i+2] = v.z; e[4*i+3] = v.w;
        }
        #pragma unroll
        for (int j = 0; j < 8; ++j) {
            uint32_t hu, lu;
            pack_hl(e[2*j], e[2*j+1], hu, lu);
            smu[WG2H + r * 20 + hf * 8 + j] = hu;
            smu[WG2L + r * 20 + hf * 8 + j] = lu;
        }
    }
    if (tid < 128) {
        float a = h2l[tid * 3], b = h2l[tid * 3 + 1], c = h2l[tid * 3 + 2];
        float sv = swl[tid];
        smf[F_H2X + tid] = a; smf[F_H2Y + tid] = b; smf[F_H2Z + tid] = c;
        smf[F_SW + tid] = sv;
        smf[F_SWM + tid] = ml[tid] ? sv : 0.0f;
    }
    if (tid < 32) smf[F_BH + tid] = bh[tid];
    if (tid < 4)  smf[F_WEQ + tid] = weq[tid];
    __syncthreads();

    // ---- WallT Q/K rows ----
    #pragma unroll 4
    for (int i = tid; i < 4096; i += THREADS) {
        int rqk = i >> 4, j = i & 15;
        int hh = rqk >> 6, r = rqk & 63;
        int c = hh * 96 + r;
        int src = (r < 32) ? r * 8 + hh : (r - 32) * 8 + 4 + hh;
        float v0 = smf[F_RQK + (2 * j) * 256 + src];
        float v1 = smf[F_RQK + (2 * j + 1) * 256 + src];
        uint32_t hu, lu;
        pack_hl(v0, v1, hu, lu);
        smu[WWTH + c * 20 + j] = hu;
        smu[WWTL + c * 20 + j] = lu;
    }
    // ---- WallT C rows: wc = wv @ wh folded per head ----
    if (tid < 128) {
        int hh = tid >> 5, m = tid & 31;
        float whcol[32];
        #pragma unroll 8
        for (int gg = 0; gg < 32; ++gg)
            whcol[gg] = smf[F_RWH + (gg * 4 + hh) * 32 + m];
        float acc[32];
        #pragma unroll 1
        for (int k = 0; k < 32; ++k) {
            const float* wvr = smf + F_RWV + k * 128 + hh;
            float s = 0.f;
            #pragma unroll
            for (int gg = 0; gg < 32; ++gg) s = fmaf(wvr[gg * 4], whcol[gg], s);
            acc[k] = s;
        }
        int c = hh * 96 + 64 + m;
        #pragma unroll
        for (int j = 0; j < 16; ++j) {
            uint32_t hu, lu;
            pack_hl(acc[2 * j], acc[2 * j + 1], hu, lu);
            smu[WWTH + c * 20 + j] = hu;
            smu[WWTL + c * 20 + j] = lu;
        }
    }
    __syncthreads();

    // ---- persistent state ----
    float oacc[4][4];
    #pragma unroll
    for (int a = 0; a < 4; ++a)
        #pragma unroll
        for (int b = 0; b < 4; ++b) oacc[a][b] = 0.f;
    float och[2][3] = {};
    float rswm[2], rh2I[2][3], rwL[2];
    #pragma unroll
    for (int mt2 = 0; mt2 < 2; ++mt2) {
        int row = m0 + g + mt2 * 8;
        rh2I[mt2][0] = smf[F_H2X + row] * INV_SQRT_D;
        rh2I[mt2][1] = smf[F_H2Y + row] * INV_SQRT_D;
        rh2I[mt2][2] = smf[F_H2Z + row] * INV_SQRT_D;
        rwL[mt2] = smf[F_SW + row] * L2E;
        rswm[mt2] = smf[F_SWM + row];
    }

    // lane-address bases (byte addrs)
    const int arow = m0 + r8 + s01 * 8;
    const uint32_t aG2h = sb + 4 * (WG2H + arow * 20 + s2 * 4);
    const uint32_t aG2l = sb + 4 * (WG2L + arow * 20 + s2 * 4);
    const uint32_t stKH = sb + 4 * (WPHH + arow * 20 + s2 * 4);
    const uint32_t stCT = sb + 4 * (WCTH + (lane & 7) * 68 + w * 8 + ((lane >> 3) & 1) * 4);
    const float C50 = -50.0f * L2E;

    #pragma unroll 1
    for (int h = 0; h < 4; ++h) {
        // ======== GEMM_P: Q(nt0-3 regs), K(nt4-7 -> smem), C(nt8-11 -> Ct) ========
        float pacc[12][4];
        #pragma unroll
        for (int a = 0; a < 12; ++a)
            #pragma unroll
            for (int b = 0; b < 4; ++b) pacc[a][b] = 0.f;
        #pragma unroll
        for (int kk = 0; kk < 2; ++kk) {
            uint32_t ah[4], al[4];
            LDSM4(ah, aG2h + 32 * kk);
            LDSM4(al, aG2l + 32 * kk);
            #pragma unroll
            for (int ntp = 0; ntp < 6; ++ntp) {
                int n = h * 96 + ntp * 16 + r8 + s2 * 8;
                uint32_t bb = sb + 4 * (WWTH + n * 20 + kk * 8 + s01 * 4);
                uint32_t bhr[4], blr[4];
                LDSM4(bhr, bb);
                LDSM4(blr, bb + 4 * (WWTL - WWTH));
                mma3(pacc[2*ntp],   ah, al, bhr[0], bhr[1], blr[0], blr[1]);
                mma3(pacc[2*ntp+1], ah, al, bhr[2], bhr[3], blr[2], blr[3]);
            }
        }
        // store K -> WPH (hi/lo) via stmatrix.x4
        #pragma unroll
        for (int ntp = 0; ntp < 2; ++ntp) {
            uint32_t h0, l0, h1, l1, h2r, l2, h3, l3;
            int nt = 4 + 2 * ntp;
            pack_hl(pacc[nt][0],   pacc[nt][1],   h0, l0);
            pack_hl(pacc[nt][2],   pacc[nt][3],   h1, l1);
            pack_hl(pacc[nt+1][0], pacc[nt+1][1], h2r, l2);
            pack_hl(pacc[nt+1][2], pacc[nt+1][3], h3, l3);
            STSM4(stKH + 32 * ntp, h0, h1, h2r, h3);
            STSM4(stKH + 32 * ntp + 4 * (WPHL - WPHH), l0, l1, l2, l3);
        }
        // store C transposed -> Ct (hi/lo)
        #pragma unroll
        for (int nt = 8; nt < 12; ++nt) {
            int j0 = (nt - 8) * 8;
            uint32_t h0, l0, h1, l1;
            pack_hl(pacc[nt][0], pacc[nt][1], h0, l0);
            pack_hl(pacc[nt][2], pacc[nt][3], h1, l1);
            uint32_t ba = stCT + 4 * (j0 * 68);
            STSM2T(ba, h0, h1);
            STSM2T(ba + 4 * (WCTL - WCTH), l0, l1);
        }
        __syncthreads();

        // ======== GEMM_S: A = Q from registers; B = K from smem ========
        float sacc[16][4];
        #pragma unroll
        for (int a = 0; a < 16; ++a)
            #pragma unroll
            for (int b = 0; b < 4; ++b) sacc[a][b] = 0.f;
        #pragma unroll
        for (int kk = 0; kk < 2; ++kk) {
            uint32_t ah[4], al[4];
            afrag_from_acc(pacc[2*kk], pacc[2*kk+1], 1.0f, 1.0f, ah, al);
            #pragma unroll
            for (int ntp = 0; ntp < 8; ++ntp) {
                int n = ntp * 16 + r8 + s2 * 8;
                uint32_t bb = sb + 4 * (WPHH + n * 20 + kk * 8 + s01 * 4);
                uint32_t bhr[4], blr[4];
                LDSM4(bhr, bb);
                LDSM4(blr, bb + 4 * (WPHL - WPHH));
                mma3(sacc[2*ntp],   ah, al, bhr[0], bhr[1], blr[0], blr[1]);
                mma3(sacc[2*ntp+1], ah, al, bhr[2], bhr[3], blr[2], blr[3]);
            }
        }

        // ======== single-pass softmax ========
        float ssum[2] = {0.f, 0.f}, ochp[2][3] = {};
        #pragma unroll
        for (int nt = 0; nt < 16; ++nt) {
            int c0 = nt * 8 + 2 * t;
            float2 hx = *(float2*)(smf + F_H2X + c0);
            float2 hy = *(float2*)(smf + F_H2Y + c0);
            float2 hz = *(float2*)(smf + F_H2Z + c0);
            float2 hw = *(float2*)(smf + F_SW + c0);
            float2 hm = *(float2*)(smf + F_SWM + c0);
            #pragma unroll
            for (int b = 0; b < 2; ++b) {
                float cx = b ? hx.y : hx.x, cy = b ? hy.y : hy.x;
                float cz = b ? hz.y : hz.x, cw = b ? hw.y : hw.x;
                float cm = b ? hm.y : hm.x;
                #pragma unroll
                for (int mt2 = 0; mt2 < 2; ++mt2) {
                    float dot = sacc[nt][mt2 * 2 + b];
                    float h2dI = fmaf(rh2I[mt2][0], cx,
                               fmaf(rh2I[mt2][1], cy, rh2I[mt2][2] * cz));
                    float t1 = fmaf(dot, h2dI, ATTNW_SHIFT);
                    float e = ex2a(fmaf(t1, cw * rwL[mt2], C50));
                    ssum[mt2] += e;
                    float ap = (e * cm) * h2dI;
                    sacc[nt][mt2 * 2 + b] = ap;
                    ochp[mt2][0] = fmaf(ap, cx, ochp[mt2][0]);
                    ochp[mt2][1] = fmaf(ap, cy, ochp[mt2][1]);
                    ochp[mt2][2] = fmaf(ap, cz, ochp[mt2][2]);
                }
            }
        }
        float rowscale[2];
        float wqh = smf[F_WEQ + h];
        #pragma unroll
        for (int mt2 = 0; mt2 < 2; ++mt2) {
            float s = ssum[mt2];
            s += __shfl_xor_sync(0xffffffffu, s, 1);
            s += __shfl_xor_sync(0xffffffffu, s, 2);
            rowscale[mt2] = rswm[mt2] * SQRT32 / (fmaxf(s, 1e-30f) * SQRT3);
            float f = wqh * rowscale[mt2];
            och[mt2][0] = fmaf(f, ochp[mt2][0], och[mt2][0]);
            och[mt2][1] = fmaf(f, ochp[mt2][1], och[mt2][1]);
            och[mt2][2] = fmaf(f, ochp[mt2][2], och[mt2][2]);
        }

        // ======== GEMM_O: A = A' from registers; B = Ct from smem ========
        #pragma unroll 2
        for (int kk = 0; kk < 8; ++kk) {
            uint32_t ah[4], al[4];
            afrag_from_acc(sacc[2*kk], sacc[2*kk+1], rowscale[0], rowscale[1], ah, al);
            #pragma unroll
            for (int ntp = 0; ntp < 2; ++ntp) {
                int n = ntp * 16 + r8 + s2 * 8;
                uint32_t bb = sb + 4 * (WCTH + n * 68 + kk * 8 + s01 * 4);
                uint32_t bhr[4], blr[4];
                LDSM4(bhr, bb);
                LDSM4(blr, bb + 4 * (WCTL - WCTH));
                mma3(oacc[2*ntp],   ah, al, bhr[0], bhr[1], blr[0], blr[1]);
                mma3(oacc[2*ntp+1], ah, al, bhr[2], bhr[3], blr[2], blr[3]);
            }
        }
        __syncthreads();   // K/Ct buffers reused next head
    }

    // ---- outputs ----
    #pragma unroll
    for (int hb = 0; hb < 2; ++hb) {
        int row = m0 + g + hb * 8;
        float* go = outg + ((size_t)loc * 128 + row) * 32;
        #pragma unroll
        for (int nt = 0; nt < 4; ++nt) {
            int col = nt * 8 + 2 * t;
            float2 v = make_float2(oacc[nt][hb * 2] + smf[F_BH + col],
                                   oacc[nt][hb * 2 + 1] + smf[F_BH + col + 1]);
            *(float2*)(go + col) = v;
        }
    }
    if (outh) {
        #pragma unroll
        for (int mt2 = 0; mt2 < 2; ++mt2) {
            #pragma unroll
            for (int c = 0; c < 3; ++c) {
                och[mt2][c] += __shfl_xor_sync(0xffffffffu, och[mt2][c], 1);
                och[mt2][c] += __shfl_xor_sync(0xffffffffu, och[mt2][c], 2);
            }
            if (t == 0) {
                int row = m0 + g + mt2 * 8;
                float* ho = outh + ((size_t)loc * 128 + row) * 3;
                ho[0] = och[mt2][0]; ho[1] = och[mt2][1]; ho[2] = och[mt2][2];
            }
        }
    }
}

extern "C" void kernel_launch(void* const* d_in, const int* in_sizes, int n_in,
                              void* d_out, int out_size) {
    const float* g2  = (const float*)d_in[0];
    const float* h2  = (const float*)d_in[1];
    const float* sw  = (const float*)d_in[2];
    const float* wqk = (const float*)d_in[3];
    const float* wv  = (const float*)d_in[4];
    const float* wh  = (const float*)d_in[5];
    const float* bh  = (const float*)d_in[6];
    const float* weq = (const float*)d_in[7];
    const int*   msk = (const int*)d_in[8];

    int nloc = in_sizes[2] / 128;
    float* outg = (float*)d_out;
    size_t gsz = (size_t)nloc * 128 * 32;
    float* outh = ((size_t)out_size >= gsz + (size_t)nloc * 128 * 3) ? outg + gsz : nullptr;

    cudaFuncSetAttribute(rep_bf16_kernel, cudaFuncAttributeMaxDynamicSharedMemorySize, SMEM_BYTES);
    rep_bf16_kernel<<<nloc, THREADS, SMEM_BYTES>>>(g2, h2, sw, wqk, wv, wh, bh, weq, msk, outg, outh);
}